// round 2
// baseline (speedup 1.0000x reference)
#include <cuda_runtime.h>
#include <math_constants.h>

#define NROWS 4096
#define S_SLOTS 200
#define X_DIM 64
#define M_DIM 364
#define O_DIM 64
#define F4 91          // M_DIM / 4
#define EPS 1e-6f
#define NT 256
#define NW 8

__global__ __launch_bounds__(NT, 4)
void mem_attn_kernel(const float* __restrict__ x,
                     const float* __restrict__ mem,
                     const float* __restrict__ W_x,
                     const float* __restrict__ b_x,
                     const float* __restrict__ W_out,
                     const float* __restrict__ b_out,
                     float* __restrict__ out)
{
    __shared__ __align__(16) float sh_x[X_DIM];
    __shared__ __align__(16) float sh_h[M_DIM];
    __shared__ __align__(16) float sh_acc[NW][M_DIM];
    __shared__ float sh_wsum[NW];
    __shared__ float sh_red[NW];
    __shared__ __align__(16) float sh_g[M_DIM];
    __shared__ float sh_out[4][O_DIM];

    const int n    = blockIdx.x;
    const int t    = threadIdx.x;
    const int lane = t & 31;
    const int w    = t >> 5;

    // ---- load x row ----
    if (t < X_DIM) sh_x[t] = x[(size_t)n * X_DIM + t];
    __syncthreads();

    // ---- h = relu(x @ W_x + b_x), and partial ||h||^2 ----
    float hn_part = 0.f;
    for (int j = t; j < M_DIM; j += NT) {
        float a = b_x[j];
        #pragma unroll 16
        for (int i = 0; i < X_DIM; i++) a = fmaf(sh_x[i], W_x[i * M_DIM + j], a);
        a = fmaxf(a, 0.f);
        sh_h[j] = a;
        hn_part = fmaf(a, a, hn_part);
    }
    #pragma unroll
    for (int o = 16; o > 0; o >>= 1) hn_part += __shfl_xor_sync(0xffffffffu, hn_part, o);
    if (lane == 0) sh_red[w] = hn_part;
    __syncthreads();
    float hsum = 0.f;
    #pragma unroll
    for (int i = 0; i < NW; i++) hsum += sh_red[i];
    const float inv_hnorm = 1.f / fmaxf(sqrtf(hsum), EPS);

    // ---- single pass over mem; cosine sim is in [-1,1] so exp(sim) is safe
    //      with NO max subtraction -> plain weighted accumulation ----
    // warp w handles slot pairs p = w, w+8, ... (pairs (2p, 2p+1)); 100 pairs.
    // Lane holds float4 chunks idx = lane, lane+32, lane+64 (valid < 91).
    float4 acc0 = make_float4(0.f, 0.f, 0.f, 0.f);
    float4 acc1 = make_float4(0.f, 0.f, 0.f, 0.f);
    float4 acc2 = make_float4(0.f, 0.f, 0.f, 0.f);
    float rsum = 0.f;

    const float* memn = mem + (size_t)n * S_SLOTS * M_DIM;
    const float4* sh_h4 = reinterpret_cast<const float4*>(sh_h);

    const bool has2 = (lane + 64) < F4;   // lanes 0..26

    const float4 h0 = sh_h4[lane];
    const float4 h1 = sh_h4[lane + 32];
    const float4 h2 = has2 ? sh_h4[lane + 64] : make_float4(0.f, 0.f, 0.f, 0.f);

    for (int p = w; p < S_SLOTS / 2; p += NW) {
        const int s = 2 * p;
        const float4* rowA = reinterpret_cast<const float4*>(memn + (size_t)s * M_DIM);
        const float4* rowB = reinterpret_cast<const float4*>(memn + (size_t)(s + 1) * M_DIM);
        float4 a0 = __ldcs(rowA + lane);
        float4 a1 = __ldcs(rowA + lane + 32);
        float4 a2 = has2 ? __ldcs(rowA + lane + 64) : make_float4(0.f, 0.f, 0.f, 0.f);
        float4 c0 = __ldcs(rowB + lane);
        float4 c1 = __ldcs(rowB + lane + 32);
        float4 c2 = has2 ? __ldcs(rowB + lane + 64) : make_float4(0.f, 0.f, 0.f, 0.f);

        float dotA = a0.x*h0.x + a0.y*h0.y + a0.z*h0.z + a0.w*h0.w
                   + a1.x*h1.x + a1.y*h1.y + a1.z*h1.z + a1.w*h1.w
                   + a2.x*h2.x + a2.y*h2.y + a2.z*h2.z + a2.w*h2.w;
        float nsqA = a0.x*a0.x + a0.y*a0.y + a0.z*a0.z + a0.w*a0.w
                   + a1.x*a1.x + a1.y*a1.y + a1.z*a1.z + a1.w*a1.w
                   + a2.x*a2.x + a2.y*a2.y + a2.z*a2.z + a2.w*a2.w;
        float dotB = c0.x*h0.x + c0.y*h0.y + c0.z*h0.z + c0.w*h0.w
                   + c1.x*h1.x + c1.y*h1.y + c1.z*h1.z + c1.w*h1.w
                   + c2.x*h2.x + c2.y*h2.y + c2.z*h2.z + c2.w*h2.w;
        float nsqB = c0.x*c0.x + c0.y*c0.y + c0.z*c0.z + c0.w*c0.w
                   + c1.x*c1.x + c1.y*c1.y + c1.z*c1.z + c1.w*c1.w
                   + c2.x*c2.x + c2.y*c2.y + c2.z*c2.z + c2.w*c2.w;

        #pragma unroll
        for (int o = 16; o > 0; o >>= 1) {
            dotA += __shfl_xor_sync(0xffffffffu, dotA, o);
            nsqA += __shfl_xor_sync(0xffffffffu, nsqA, o);
            dotB += __shfl_xor_sync(0xffffffffu, dotB, o);
            nsqB += __shfl_xor_sync(0xffffffffu, nsqB, o);
        }

        const float simA = dotA * inv_hnorm / fmaxf(sqrtf(nsqA), EPS);
        const float simB = dotB * inv_hnorm / fmaxf(sqrtf(nsqB), EPS);
        const float eA = __expf(simA);
        const float eB = __expf(simB);
        rsum += eA + eB;

        acc0.x = fmaf(eA, a0.x, fmaf(eB, c0.x, acc0.x));
        acc0.y = fmaf(eA, a0.y, fmaf(eB, c0.y, acc0.y));
        acc0.z = fmaf(eA, a0.z, fmaf(eB, c0.z, acc0.z));
        acc0.w = fmaf(eA, a0.w, fmaf(eB, c0.w, acc0.w));
        acc1.x = fmaf(eA, a1.x, fmaf(eB, c1.x, acc1.x));
        acc1.y = fmaf(eA, a1.y, fmaf(eB, c1.y, acc1.y));
        acc1.z = fmaf(eA, a1.z, fmaf(eB, c1.z, acc1.z));
        acc1.w = fmaf(eA, a1.w, fmaf(eB, c1.w, acc1.w));
        acc2.x = fmaf(eA, a2.x, fmaf(eB, c2.x, acc2.x));
        acc2.y = fmaf(eA, a2.y, fmaf(eB, c2.y, acc2.y));
        acc2.z = fmaf(eA, a2.z, fmaf(eB, c2.z, acc2.z));
        acc2.w = fmaf(eA, a2.w, fmaf(eB, c2.w, acc2.w));
    }

    // ---- merge warps (plain sums; shared shift of 0 cancels) ----
    if (lane == 0) sh_wsum[w] = rsum;

    float4* dst = reinterpret_cast<float4*>(sh_acc[w]);
    dst[lane]      = acc0;
    dst[lane + 32] = acc1;
    if (has2) dst[lane + 64] = acc2;
    __syncthreads();

    float total = 0.f;
    #pragma unroll
    for (int i = 0; i < NW; i++) total += sh_wsum[i];

    const float inv = 1.f / (total * (float)S_SLOTS);
    for (int j = t; j < M_DIM; j += NT) {
        float p = 0.f;
        #pragma unroll
        for (int i = 0; i < NW; i++) p += sh_acc[i][j];
        sh_g[j] = p * inv * sh_h[j];
    }
    __syncthreads();

    // ---- out = relu((pooled*h) @ W_out + b_out) ----
    {
        const int oc = t & 63;
        const int c  = t >> 6;           // 4 chunks of 91
        float a = 0.f;
        const int m0 = c * F4;
        #pragma unroll 13
        for (int m = m0; m < m0 + F4; m++) a = fmaf(sh_g[m], W_out[m * O_DIM + oc], a);
        sh_out[c][oc] = a;
    }
    __syncthreads();
    if (t < O_DIM) {
        float a = sh_out[0][t] + sh_out[1][t] + sh_out[2][t] + sh_out[3][t] + b_out[t];
        out[(size_t)n * O_DIM + t] = fmaxf(a, 0.f);
    }
}

extern "C" void kernel_launch(void* const* d_in, const int* in_sizes, int n_in,
                              void* d_out, int out_size)
{
    const float* x     = (const float*)d_in[0];
    const float* mem   = (const float*)d_in[1];
    const float* W_x   = (const float*)d_in[2];
    const float* b_x   = (const float*)d_in[3];
    const float* W_out = (const float*)d_in[4];
    const float* b_out = (const float*)d_in[5];
    float* out = (float*)d_out;

    mem_attn_kernel<<<NROWS, NT>>>(x, mem, W_x, b_x, W_out, b_out, out);
}

// round 3
// speedup vs baseline: 1.0383x; 1.0383x over previous
#include <cuda_runtime.h>

#define NROWS   4096
#define S_SLOTS 200
#define X_DIM   64
#define M_DIM   364
#define O_DIM   64
#define F4      91                    // M_DIM / 4
#define EPS     1e-6f
#define NT      256
#define NW      8

#define SLOT_B      (M_DIM * 4)           // 1456 bytes per slot
#define STAGE_SLOTS 8
#define STAGE_F4    (STAGE_SLOTS * F4)    // 728 float4 per stage
#define STAGE_B     (STAGE_SLOTS * SLOT_B) // 11648 bytes per stage
#define NSTAGES     (S_SLOTS / STAGE_SLOTS) // 25
#define DEPTH       3

__global__ __launch_bounds__(NT)
void mem_attn_kernel(const float* __restrict__ x,
                     const float* __restrict__ mem,
                     const float* __restrict__ W_x,
                     const float* __restrict__ b_x,
                     const float* __restrict__ W_out,
                     const float* __restrict__ b_out,
                     float* __restrict__ out)
{
    __shared__ __align__(16) char  sbuf[DEPTH * STAGE_B];   // 34944 B
    __shared__ __align__(16) float sh_h[M_DIM];
    __shared__ float sh_x[X_DIM];
    __shared__ float sh_red[NW];
    __shared__ float sh_wsum[NW];

    const int n    = blockIdx.x;
    const int t    = threadIdx.x;
    const int lane = t & 31;
    const int w    = t >> 5;

    const float* memn = mem + (size_t)n * S_SLOTS * M_DIM;

    // ---- kick off the first DEPTH stage copies immediately ----
    #pragma unroll
    for (int st = 0; st < DEPTH; st++) {
        const char* gsrc = (const char*)memn + (size_t)st * STAGE_B;
        unsigned sdst = (unsigned)__cvta_generic_to_shared(sbuf + st * STAGE_B);
        for (int j = t; j < STAGE_F4; j += NT) {
            asm volatile("cp.async.cg.shared.global [%0], [%1], 16;"
                         :: "r"(sdst + j * 16), "l"(gsrc + j * 16));
        }
        asm volatile("cp.async.commit_group;");
    }

    // ---- load x row, compute h = relu(x @ W_x + b_x) and ||h|| ----
    if (t < X_DIM) sh_x[t] = x[(size_t)n * X_DIM + t];
    __syncthreads();

    float hn_part = 0.f;
    for (int j = t; j < M_DIM; j += NT) {
        float a = b_x[j];
        #pragma unroll 16
        for (int i = 0; i < X_DIM; i++) a = fmaf(sh_x[i], W_x[i * M_DIM + j], a);
        a = fmaxf(a, 0.f);
        sh_h[j] = a;
        hn_part = fmaf(a, a, hn_part);
    }
    #pragma unroll
    for (int o = 16; o > 0; o >>= 1) hn_part += __shfl_xor_sync(0xffffffffu, hn_part, o);
    if (lane == 0) sh_red[w] = hn_part;
    __syncthreads();
    float hsum = 0.f;
    #pragma unroll
    for (int i = 0; i < NW; i++) hsum += sh_red[i];
    const float inv_hnorm = 1.f / fmaxf(sqrtf(hsum), EPS);

    const float4* sh_h4 = reinterpret_cast<const float4*>(sh_h);
    const bool has2 = (lane + 64) < F4;   // lanes 0..26
    const float4 h0 = sh_h4[lane];
    const float4 h1 = sh_h4[lane + 32];
    const float4 h2 = has2 ? sh_h4[lane + 64] : make_float4(0.f, 0.f, 0.f, 0.f);

    // ---- streamed mainloop: warp w computes slot (st*8 + w) of each stage ----
    float4 acc0 = make_float4(0.f, 0.f, 0.f, 0.f);
    float4 acc1 = make_float4(0.f, 0.f, 0.f, 0.f);
    float4 acc2 = make_float4(0.f, 0.f, 0.f, 0.f);
    float rsum = 0.f;

    for (int st = 0; st < NSTAGES; st++) {
        asm volatile("cp.async.wait_group 2;");   // stage st (oldest) complete
        __syncthreads();

        const float4* slot = reinterpret_cast<const float4*>(
            sbuf + (st % DEPTH) * STAGE_B + w * SLOT_B);
        float4 v0 = slot[lane];
        float4 v1 = slot[lane + 32];
        float4 v2 = has2 ? slot[lane + 64] : make_float4(0.f, 0.f, 0.f, 0.f);

        float dot = v0.x*h0.x + v0.y*h0.y + v0.z*h0.z + v0.w*h0.w
                  + v1.x*h1.x + v1.y*h1.y + v1.z*h1.z + v1.w*h1.w
                  + v2.x*h2.x + v2.y*h2.y + v2.z*h2.z + v2.w*h2.w;
        float nsq = v0.x*v0.x + v0.y*v0.y + v0.z*v0.z + v0.w*v0.w
                  + v1.x*v1.x + v1.y*v1.y + v1.z*v1.z + v1.w*v1.w
                  + v2.x*v2.x + v2.y*v2.y + v2.z*v2.z + v2.w*v2.w;
        #pragma unroll
        for (int o = 16; o > 0; o >>= 1) {
            dot += __shfl_xor_sync(0xffffffffu, dot, o);
            nsq += __shfl_xor_sync(0xffffffffu, nsq, o);
        }

        // cosine sim in [-1,1] -> exp() safe without max subtraction
        const float sim = dot * inv_hnorm / fmaxf(sqrtf(nsq), EPS);
        const float e = __expf(sim);
        rsum += e;

        acc0.x = fmaf(e, v0.x, acc0.x); acc0.y = fmaf(e, v0.y, acc0.y);
        acc0.z = fmaf(e, v0.z, acc0.z); acc0.w = fmaf(e, v0.w, acc0.w);
        acc1.x = fmaf(e, v1.x, acc1.x); acc1.y = fmaf(e, v1.y, acc1.y);
        acc1.z = fmaf(e, v1.z, acc1.z); acc1.w = fmaf(e, v1.w, acc1.w);
        acc2.x = fmaf(e, v2.x, acc2.x); acc2.y = fmaf(e, v2.y, acc2.y);
        acc2.z = fmaf(e, v2.z, acc2.z); acc2.w = fmaf(e, v2.w, acc2.w);

        __syncthreads();   // everyone done reading buffer (st % DEPTH)

        const int nst = st + DEPTH;
        if (nst < NSTAGES) {
            const char* gsrc = (const char*)memn + (size_t)nst * STAGE_B;
            unsigned sdst = (unsigned)__cvta_generic_to_shared(sbuf + (st % DEPTH) * STAGE_B);
            for (int j = t; j < STAGE_F4; j += NT) {
                asm volatile("cp.async.cg.shared.global [%0], [%1], 16;"
                             :: "r"(sdst + j * 16), "l"(gsrc + j * 16));
            }
        }
        asm volatile("cp.async.commit_group;");   // empty groups keep count consistent
    }

    // ---- merge warps; reuse retired stage buffers as scratch ----
    float* accbuf = reinterpret_cast<float*>(sbuf);                 // [NW][M_DIM]
    float* g      = reinterpret_cast<float*>(sbuf + STAGE_B);       // [M_DIM]
    float (*outb)[O_DIM] = reinterpret_cast<float (*)[O_DIM]>(sbuf + 2 * STAGE_B);

    if (lane == 0) sh_wsum[w] = rsum;
    {
        float4* dst = reinterpret_cast<float4*>(accbuf + w * M_DIM);
        dst[lane]      = acc0;
        dst[lane + 32] = acc1;
        if (has2) dst[lane + 64] = acc2;
    }
    __syncthreads();

    float total = 0.f;
    #pragma unroll
    for (int i = 0; i < NW; i++) total += sh_wsum[i];

    const float inv = 1.f / (total * (float)S_SLOTS);
    for (int j = t; j < M_DIM; j += NT) {
        float p = 0.f;
        #pragma unroll
        for (int i = 0; i < NW; i++) p += accbuf[i * M_DIM + j];
        g[j] = p * inv * sh_h[j];
    }
    __syncthreads();

    // ---- out = relu((pooled*h) @ W_out + b_out) ----
    {
        const int oc = t & 63;
        const int c  = t >> 6;           // 4 chunks of 91
        float a = 0.f;
        const int m0 = c * F4;
        #pragma unroll 13
        for (int m = m0; m < m0 + F4; m++) a = fmaf(g[m], W_out[m * O_DIM + oc], a);
        outb[c][oc] = a;
    }
    __syncthreads();
    if (t < O_DIM) {
        float a = outb[0][t] + outb[1][t] + outb[2][t] + outb[3][t] + b_out[t];
        out[(size_t)n * O_DIM + t] = fmaxf(a, 0.f);
    }
}

extern "C" void kernel_launch(void* const* d_in, const int* in_sizes, int n_in,
                              void* d_out, int out_size)
{
    const float* x     = (const float*)d_in[0];
    const float* mem   = (const float*)d_in[1];
    const float* W_x   = (const float*)d_in[2];
    const float* b_x   = (const float*)d_in[3];
    const float* W_out = (const float*)d_in[4];
    const float* b_out = (const float*)d_in[5];
    float* out = (float*)d_out;

    mem_attn_kernel<<<NROWS, NT>>>(x, mem, W_x, b_x, W_out, b_out, out);
}